// round 7
// baseline (speedup 1.0000x reference)
#include <cuda_runtime.h>
#include <cstdint>
#include <cstddef>

#define B_SZ 8
#define L_SZ 12288
#define F_SZ 512
#define NTHREADS 512
#define M_TILE 64
#define N_TILES_CTA 192   /* L / M_TILE */

// tf32-rounded copy of the conv kernel weights (25MB static device scratch)
__device__ float g_Ktf[(size_t)F_SZ * L_SZ];

// ---------------- helpers ----------------
__device__ __forceinline__ uint32_t smem_u32(const void* p) {
    uint32_t a;
    asm("{ .reg .u64 t; cvta.to.shared.u64 t, %1; cvt.u32.u64 %0, t; }" : "=r"(a) : "l"(p));
    return a;
}
#define SWZ128(o) ((o) ^ (((o) >> 3) & 0x70))

#define CP16(dst, src) \
    asm volatile("cp.async.cg.shared.global [%0], [%1], 16;" :: "r"(dst), "l"(src))
#define CP_COMMIT() asm volatile("cp.async.commit_group;" ::: "memory")
#define CP_WAIT(N) asm volatile("cp.async.wait_group %0;" :: "n"(N) : "memory")

__device__ __forceinline__ void ldsm4(uint32_t* r, uint32_t addr) {
    asm volatile("ldmatrix.sync.aligned.m8n8.x4.shared.b16 {%0,%1,%2,%3}, [%4];"
                 : "=r"(r[0]), "=r"(r[1]), "=r"(r[2]), "=r"(r[3]) : "r"(addr));
}

__device__ __forceinline__ void mma8(float* c, const uint32_t* a, uint32_t b0, uint32_t b1) {
    asm volatile(
        "mma.sync.aligned.m16n8k8.row.col.f32.tf32.tf32.f32 "
        "{%0,%1,%2,%3}, {%4,%5,%6,%7}, {%8,%9}, {%0,%1,%2,%3};"
        : "+f"(c[0]), "+f"(c[1]), "+f"(c[2]), "+f"(c[3])
        : "r"(a[0]), "r"(a[1]), "r"(a[2]), "r"(a[3]), "r"(b0), "r"(b1));
}

// ---------------- preprocess: round K to tf32 (round-to-nearest) ----------------
__global__ void round_tf32_kernel(const float* __restrict__ K) {
    size_t i = (size_t)blockIdx.x * blockDim.x + threadIdx.x;
    if (i < (size_t)F_SZ * L_SZ) {
        float v = K[i];
        uint32_t u;
        asm("cvt.rna.tf32.f32 %0, %1;" : "=r"(u) : "f"(v));
        g_Ktf[i] = __uint_as_float(u);
    }
}

// ---------------- SMEM layout (bytes from dynamic smem base) ----------------
#define OFF_BIAS    0u        /* 512*4  = 2048  */
#define OFF_W       2048u     /* 512*16 = 8192  -> 10240 */
#define OFF_X       10240u    /* 12288*4= 49152 -> 59392 */
#define OFF_A       59392u    /* 2 * 8192  = 16384 -> 75776  (1024-aligned) */
#define OFF_B       75776u    /* 2 * 65536 = 131072 -> 206848 (1024-aligned) */
#define A_STRIDE    8192u
#define B_STRIDE    65536u
#define SMEM_TOTAL  206848u

// ---------------- main fused kernel ----------------
__global__ void __launch_bounds__(NTHREADS, 1)
conv_fused_kernel(const int* __restrict__ example,
                  const float* __restrict__ bias,
                  const float* __restrict__ dense_w,
                  const float* __restrict__ dense_b,
                  float* __restrict__ out) {
    extern __shared__ char smem[];
    const uint32_t smem_base = smem_u32(smem);
    const int tid = threadIdx.x;
    const int wid = tid >> 5;
    const int lane = tid & 31;
    const int wm = wid >> 3;       // 0..1  (M position: 32 rows per warp)
    const int wn = wid & 7;        // 0..7  (N position: 64 filters per warp)

    // LPT schedule: heavy tiles (large T0) first
    const int i_tile = (N_TILES_CTA - 1) - (int)(blockIdx.x >> 3);
    const int b = (int)(blockIdx.x & 7);
    const int T0 = i_tile * M_TILE;
    const int C = (T0 >> 5) + 2;   // 32-wide j-chunks needed (j <= T0+63)

    // ---- stage bias, dense_w, x into SMEM ----
    {
        float* bs = (float*)(smem + OFF_BIAS);
        for (int f = tid; f < F_SZ; f += NTHREADS) bs[f] = bias[f];
        float4* ws = (float4*)(smem + OFF_W);
        const float4* wg = (const float4*)dense_w;
        for (int f = tid; f < F_SZ; f += NTHREADS) ws[f] = wg[f];
        const int4* e4 = (const int4*)(example + (size_t)b * L_SZ);
        float4* xs4 = (float4*)(smem + OFF_X);
        for (int k = tid; k < L_SZ / 4; k += NTHREADS) {
            int4 v = e4[k];
            float4 f;
            f.x = (float)v.x * 0.5f - 1.0f;
            f.y = (float)v.y * 0.5f - 1.0f;
            f.z = (float)v.z * 0.5f - 1.0f;
            f.w = (float)v.w * 0.5f - 1.0f;
            xs4[k] = f;
        }
    }
    __syncthreads();

    const float* xs = (const float*)(smem + OFF_X);

    // ---- precomputed ldmatrix lane offsets ----
    // Correct SW128 composition: addr = rowbase + ((colbyte) ^ swz), swz = (rowbase>>3)&0x70.
    // colbyte = static part + kk*32; static (bit 4) and kk*32 (bits 5-6) are disjoint,
    // so precompute pre = rowbase + (static_col ^ swz) and use pre ^ (kk*32) at the call.
    //
    // A frag (m16 tile mt): row = wm*32 + mt*16 + (lane&15); static col byte = ((lane>>4)<<4)
    uint32_t a_pre[2];
    #pragma unroll
    for (int mt = 0; mt < 2; mt++) {
        uint32_t rowbase = (uint32_t)(wm * 32 + mt * 16 + (lane & 15)) * 128u;
        uint32_t swz = (rowbase >> 3) & 0x70u;
        uint32_t col = (uint32_t)((lane >> 4) << 4);
        a_pre[mt] = rowbase + (col ^ swz);
    }
    // B frag (n16 group g): n = wn*64 + g*16 + (lane&7) + (((lane>>4)&1)<<3);
    // static col byte = ((lane>>3)&1)<<4
    uint32_t b_pre[4];
    #pragma unroll
    for (int g = 0; g < 4; g++) {
        uint32_t n = (uint32_t)(wn * 64 + g * 16 + (lane & 7) + (((lane >> 4) & 1) << 3));
        uint32_t rowbase = n * 128u;
        uint32_t swz = (rowbase >> 3) & 0x70u;
        uint32_t col = (uint32_t)(((lane >> 3) & 1) << 4);
        b_pre[g] = rowbase + (col ^ swz);
    }

    // A build mapping: thread t covers row = t>>3, cols (t&7)*4 .. +3
    const int arow = tid >> 3;
    const int acol = (tid & 7) * 4;

    float acc[2][8][4];
    #pragma unroll
    for (int mt = 0; mt < 2; mt++)
        #pragma unroll
        for (int nt = 0; nt < 8; nt++)
            #pragma unroll
            for (int k = 0; k < 4; k++) acc[mt][nt][k] = 0.0f;

    // ---- prologue: stage 0 <- chunk 0 ----
    {
        char* Ab = smem + OFF_A;
        int i0 = T0 + arow - acol;   // J0 = 0
        float4 v;
        v.x = (i0 >= 0) ? xs[i0]     : 0.0f;
        v.y = (i0 >= 1) ? xs[i0 - 1] : 0.0f;
        v.z = (i0 >= 2) ? xs[i0 - 2] : 0.0f;
        v.w = (i0 >= 3) ? xs[i0 - 3] : 0.0f;
        *(float4*)(Ab + SWZ128((uint32_t)(arow * 128 + acol * 4))) = v;

        #pragma unroll
        for (int q = 0; q < 8; q++) {
            int linear = tid + q * NTHREADS;      // 0..4095
            int f = linear >> 3;
            int ch = linear & 7;
            const char* src = (const char*)g_Ktf + (size_t)f * (L_SZ * 4) + (size_t)ch * 16;
            uint32_t dst = smem_base + OFF_B + SWZ128((uint32_t)(f * 128 + ch * 16));
            CP16(dst, src);
        }
        CP_COMMIT();
    }

    // ---- mainloop ----
    for (int c = 0; c < C; c++) {
        const int s = c & 1;
        const int ns = s ^ 1;

        if (c + 1 < C) {
            // build chunk c+1 into stage ns (stage ns free: compute of c-1 synced)
            const int J1 = (c + 1) * 32;
            char* Ab = smem + OFF_A + ns * A_STRIDE;
            int i0 = T0 + arow - J1 - acol;
            float4 v;
            v.x = (i0 >= 0) ? xs[i0]     : 0.0f;
            v.y = (i0 >= 1) ? xs[i0 - 1] : 0.0f;
            v.z = (i0 >= 2) ? xs[i0 - 2] : 0.0f;
            v.w = (i0 >= 3) ? xs[i0 - 3] : 0.0f;
            *(float4*)(Ab + SWZ128((uint32_t)(arow * 128 + acol * 4))) = v;

            #pragma unroll
            for (int q = 0; q < 8; q++) {
                int linear = tid + q * NTHREADS;
                int f = linear >> 3;
                int ch = linear & 7;
                const char* src = (const char*)g_Ktf + (size_t)f * (L_SZ * 4)
                                + (size_t)J1 * 4 + (size_t)ch * 16;
                uint32_t dst = smem_base + OFF_B + (uint32_t)ns * B_STRIDE
                             + SWZ128((uint32_t)(f * 128 + ch * 16));
                CP16(dst, src);
            }
            CP_COMMIT();
            CP_WAIT(1);    // chunk c's B complete; c+1 in flight
        } else {
            CP_WAIT(0);
        }
        __syncthreads();   // B[c] visible, A[c+1] built, stage s safe to read

        const uint32_t abase = smem_base + OFF_A + (uint32_t)s * A_STRIDE;
        const uint32_t bbase = smem_base + OFF_B + (uint32_t)s * B_STRIDE;

        #pragma unroll
        for (int kk = 0; kk < 4; kk++) {
            const uint32_t kx = (uint32_t)(kk * 32);
            uint32_t afr[2][4];
            #pragma unroll
            for (int mt = 0; mt < 2; mt++)
                ldsm4(afr[mt], abase + (a_pre[mt] ^ kx));
            uint32_t bfr[4][4];
            #pragma unroll
            for (int g = 0; g < 4; g++)
                ldsm4(bfr[g], bbase + (b_pre[g] ^ kx));
            #pragma unroll
            for (int mt = 0; mt < 2; mt++)
                #pragma unroll
                for (int nt = 0; nt < 8; nt++)
                    mma8(acc[mt][nt], afr[mt], bfr[nt >> 1][(nt & 1) * 2],
                         bfr[nt >> 1][(nt & 1) * 2 + 1]);
        }
        __syncthreads();   // all warps done with stage s before next build
    }

    // ---- fused epilogue: bias + ReLU + dense[512x4] ----
    {
        const float* bs = (const float*)(smem + OFF_BIAS);
        const float4* ws = (const float4*)(smem + OFF_W);
        const int g = lane >> 2;
        const int cp = lane & 3;

        // per-thread partials for 4 row contexts (mt,h): rows wm*32 + mt*16 + h*8 + g
        float4 part[2][2];
        #pragma unroll
        for (int mt = 0; mt < 2; mt++)
            #pragma unroll
            for (int h = 0; h < 2; h++) {
                float4 p = make_float4(0.f, 0.f, 0.f, 0.f);
                #pragma unroll
                for (int nt = 0; nt < 8; nt++) {
                    int f0 = wn * 64 + nt * 8 + 2 * cp;
                    float v0 = fmaxf(acc[mt][nt][h * 2 + 0] + bs[f0], 0.0f);
                    float v1 = fmaxf(acc[mt][nt][h * 2 + 1] + bs[f0 + 1], 0.0f);
                    float4 w0 = ws[f0];
                    float4 w1 = ws[f0 + 1];
                    p.x += v0 * w0.x + v1 * w1.x;
                    p.y += v0 * w0.y + v1 * w1.y;
                    p.z += v0 * w0.z + v1 * w1.z;
                    p.w += v0 * w0.w + v1 * w1.w;
                }
                part[mt][h] = p;
            }
        // reduce over the 4 lanes sharing a row (cp = lane&3)
        #pragma unroll
        for (int mt = 0; mt < 2; mt++)
            #pragma unroll
            for (int h = 0; h < 2; h++) {
                #pragma unroll
                for (int d = 1; d < 4; d <<= 1) {
                    part[mt][h].x += __shfl_xor_sync(0xFFFFFFFF, part[mt][h].x, d);
                    part[mt][h].y += __shfl_xor_sync(0xFFFFFFFF, part[mt][h].y, d);
                    part[mt][h].z += __shfl_xor_sync(0xFFFFFFFF, part[mt][h].z, d);
                    part[mt][h].w += __shfl_xor_sync(0xFFFFFFFF, part[mt][h].w, d);
                }
            }
        __syncthreads();   // done reading A stages; reuse OFF_A as P buffer
        float4* P = (float4*)(smem + OFF_A);   // [64 rows][8 wn]
        if (cp == 0) {
            #pragma unroll
            for (int mt = 0; mt < 2; mt++)
                #pragma unroll
                for (int h = 0; h < 2; h++) {
                    int row = wm * 32 + mt * 16 + h * 8 + g;
                    P[row * 8 + wn] = part[mt][h];
                }
        }
        __syncthreads();

        if (tid < M_TILE) {
            float4 db = *(const float4*)dense_b;
            float4 o = db;
            #pragma unroll
            for (int w = 0; w < 8; w++) {
                float4 p = P[tid * 8 + w];
                o.x += p.x; o.y += p.y; o.z += p.z; o.w += p.w;
            }
            ((float4*)out)[(size_t)b * L_SZ + T0 + tid] = o;
        }
    }
}

extern "C" void kernel_launch(void* const* d_in, const int* in_sizes, int n_in,
                              void* d_out, int out_size) {
    const int*   example = (const int*)d_in[0];
    const float* kern    = (const float*)d_in[1];
    const float* bias    = (const float*)d_in[2];
    const float* dense_w = (const float*)d_in[3];
    const float* dense_b = (const float*)d_in[4];
    float* out = (float*)d_out;

    cudaFuncSetAttribute(conv_fused_kernel,
                         cudaFuncAttributeMaxDynamicSharedMemorySize, SMEM_TOTAL);

    // 1) round conv weights to tf32-RN into static scratch
    {
        size_t n = (size_t)F_SZ * L_SZ;
        int blocks = (int)((n + 255) / 256);
        round_tf32_kernel<<<blocks, 256>>>(kern);
    }
    // 2) fused Toeplitz-GEMM + bias + ReLU + dense
    conv_fused_kernel<<<B_SZ * N_TILES_CTA, NTHREADS, SMEM_TOTAL>>>(
        example, bias, dense_w, dense_b, out);
}

// round 9
// speedup vs baseline: 1.8751x; 1.8751x over previous
#include <cuda_runtime.h>
#include <cuda_fp16.h>
#include <cstdint>
#include <cstddef>

#define B_SZ 8
#define L_SZ 12288
#define F_SZ 512
#define NTHREADS 512
#define M_TILE 64
#define N_TILES_CTA 192   /* L / M_TILE */
#define KC 64             /* k elements per stage (128B rows in fp16) */

// fp16-rounded copy of the conv kernel weights (12.5MB static device scratch)
__device__ __half g_Khf[(size_t)F_SZ * L_SZ];

// ---------------- helpers ----------------
__device__ __forceinline__ uint32_t smem_u32(const void* p) {
    uint32_t a;
    asm("{ .reg .u64 t; cvta.to.shared.u64 t, %1; cvt.u32.u64 %0, t; }" : "=r"(a) : "l"(p));
    return a;
}
#define SWZ128(o) ((o) ^ (((o) >> 3) & 0x70))

#define CP16(dst, src) \
    asm volatile("cp.async.cg.shared.global [%0], [%1], 16;" :: "r"(dst), "l"(src))
#define CP_COMMIT() asm volatile("cp.async.commit_group;" ::: "memory")
#define CP_WAIT(N) asm volatile("cp.async.wait_group %0;" :: "n"(N) : "memory")

__device__ __forceinline__ void ldsm4(uint32_t* r, uint32_t addr) {
    asm volatile("ldmatrix.sync.aligned.m8n8.x4.shared.b16 {%0,%1,%2,%3}, [%4];"
                 : "=r"(r[0]), "=r"(r[1]), "=r"(r[2]), "=r"(r[3]) : "r"(addr));
}

__device__ __forceinline__ void mma16(float* c, const uint32_t* a, uint32_t b0, uint32_t b1) {
    asm volatile(
        "mma.sync.aligned.m16n8k16.row.col.f32.f16.f16.f32 "
        "{%0,%1,%2,%3}, {%4,%5,%6,%7}, {%8,%9}, {%0,%1,%2,%3};"
        : "+f"(c[0]), "+f"(c[1]), "+f"(c[2]), "+f"(c[3])
        : "r"(a[0]), "r"(a[1]), "r"(a[2]), "r"(a[3]), "r"(b0), "r"(b1));
}

// ---------------- preprocess: round K to fp16 (round-to-nearest) ----------------
__global__ void round_fp16_kernel(const float* __restrict__ K) {
    size_t i = (size_t)blockIdx.x * blockDim.x + threadIdx.x;
    if (i < (size_t)F_SZ * L_SZ) {
        g_Khf[i] = __float2half_rn(K[i]);
    }
}

// ---------------- SMEM layout (bytes from dynamic smem base) ----------------
#define OFF_BIAS    0u        /* 512*4  = 2048  */
#define OFF_W       2048u     /* 512*16 = 8192  -> 10240 */
#define OFF_X       10240u    /* 12288*4= 49152 -> 59392 */
#define OFF_A       59392u    /* 2 * 8192  = 16384 -> 75776  (1024-aligned) */
#define OFF_B       75776u    /* 2 * 65536 = 131072 -> 206848 (1024-aligned) */
#define A_STRIDE    8192u
#define B_STRIDE    65536u
#define SMEM_TOTAL  206848u

// ---------------- main fused kernel ----------------
__global__ void __launch_bounds__(NTHREADS, 1)
conv_fused_kernel(const int* __restrict__ example,
                  const float* __restrict__ bias,
                  const float* __restrict__ dense_w,
                  const float* __restrict__ dense_b,
                  float* __restrict__ out) {
    extern __shared__ char smem[];
    const uint32_t smem_base = smem_u32(smem);
    const int tid = threadIdx.x;
    const int wid = tid >> 5;
    const int lane = tid & 31;
    const int wm = wid >> 3;       // 0..1  (M position: 32 rows per warp)
    const int wn = wid & 7;        // 0..7  (N position: 64 filters per warp)

    // LPT schedule: heavy tiles (large T0) first
    const int i_tile = (N_TILES_CTA - 1) - (int)(blockIdx.x >> 3);
    const int b = (int)(blockIdx.x & 7);
    const int T0 = i_tile * M_TILE;
    const int C = (T0 >> 6) + 1;   // 64-wide j-chunks needed (j <= T0+63)

    // ---- stage bias, dense_w, x into SMEM ----
    {
        float* bs = (float*)(smem + OFF_BIAS);
        for (int f = tid; f < F_SZ; f += NTHREADS) bs[f] = bias[f];
        float4* ws = (float4*)(smem + OFF_W);
        const float4* wg = (const float4*)dense_w;
        for (int f = tid; f < F_SZ; f += NTHREADS) ws[f] = wg[f];
        const int4* e4 = (const int4*)(example + (size_t)b * L_SZ);
        float4* xs4 = (float4*)(smem + OFF_X);
        for (int k = tid; k < L_SZ / 4; k += NTHREADS) {
            int4 v = e4[k];
            float4 f;
            f.x = (float)v.x * 0.5f - 1.0f;
            f.y = (float)v.y * 0.5f - 1.0f;
            f.z = (float)v.z * 0.5f - 1.0f;
            f.w = (float)v.w * 0.5f - 1.0f;
            xs4[k] = f;
        }
    }
    __syncthreads();

    const float* xs = (const float*)(smem + OFF_X);

    // ---- precomputed ldmatrix lane offsets (SW128 XOR-composed) ----
    // addr = rowbase + ((colbyte) ^ swz); colbyte = static ^ kk*32 (disjoint bits)
    // A frag (m16 tile mt): row = wm*32 + mt*16 + (lane&15); static col = ((lane>>4)<<4)
    uint32_t a_pre[2];
    #pragma unroll
    for (int mt = 0; mt < 2; mt++) {
        uint32_t rowbase = (uint32_t)(wm * 32 + mt * 16 + (lane & 15)) * 128u;
        uint32_t swz = (rowbase >> 3) & 0x70u;
        uint32_t col = (uint32_t)((lane >> 4) << 4);
        a_pre[mt] = rowbase + (col ^ swz);
    }
    // B frag (n16 group g): n = wn*64 + g*16 + (lane&7) + (((lane>>4)&1)<<3);
    // static col byte = ((lane>>3)&1)<<4
    uint32_t b_pre[4];
    #pragma unroll
    for (int g = 0; g < 4; g++) {
        uint32_t n = (uint32_t)(wn * 64 + g * 16 + (lane & 7) + (((lane >> 4) & 1) << 3));
        uint32_t rowbase = n * 128u;
        uint32_t swz = (rowbase >> 3) & 0x70u;
        uint32_t col = (uint32_t)(((lane >> 3) & 1) << 4);
        b_pre[g] = rowbase + (col ^ swz);
    }

    // A build mapping: thread t covers row = t>>3, k-cols (t&7)*8 .. +7 (16 bytes fp16)
    const int arow = tid >> 3;
    const int acol = (tid & 7) * 8;

    float acc[2][8][4];
    #pragma unroll
    for (int mt = 0; mt < 2; mt++)
        #pragma unroll
        for (int nt = 0; nt < 8; nt++)
            #pragma unroll
            for (int k = 0; k < 4; k++) acc[mt][nt][k] = 0.0f;

    // ---- prologue: stage 0 <- chunk 0 ----
    {
        char* Ab = smem + OFF_A;
        int i0 = T0 + arow - acol;   // J0 = 0
        __half h[8];
        #pragma unroll
        for (int ii = 0; ii < 8; ii++) {
            int idx = i0 - ii;
            h[ii] = __float2half_rn((idx >= 0) ? xs[idx] : 0.0f);
        }
        *(uint4*)(Ab + SWZ128((uint32_t)(arow * 128 + acol * 2))) = *(const uint4*)h;

        #pragma unroll
        for (int q = 0; q < 8; q++) {
            int linear = tid + q * NTHREADS;      // 0..4095
            int f = linear >> 3;
            int ch = linear & 7;
            const char* src = (const char*)g_Khf + (size_t)f * (L_SZ * 2) + (size_t)ch * 16;
            uint32_t dst = smem_base + OFF_B + SWZ128((uint32_t)(f * 128 + ch * 16));
            CP16(dst, src);
        }
        CP_COMMIT();
    }

    // ---- mainloop ----
    for (int c = 0; c < C; c++) {
        const int s = c & 1;
        const int ns = s ^ 1;

        if (c + 1 < C) {
            // build chunk c+1 into stage ns (stage ns free: compute of c-1 synced)
            const int J1 = (c + 1) * KC;
            char* Ab = smem + OFF_A + ns * A_STRIDE;
            int i0 = T0 + arow - J1 - acol;
            __half h[8];
            #pragma unroll
            for (int ii = 0; ii < 8; ii++) {
                int idx = i0 - ii;
                h[ii] = __float2half_rn((idx >= 0) ? xs[idx] : 0.0f);
            }
            *(uint4*)(Ab + SWZ128((uint32_t)(arow * 128 + acol * 2))) = *(const uint4*)h;

            #pragma unroll
            for (int q = 0; q < 8; q++) {
                int linear = tid + q * NTHREADS;
                int f = linear >> 3;
                int ch = linear & 7;
                const char* src = (const char*)g_Khf + (size_t)f * (L_SZ * 2)
                                + (size_t)J1 * 2 + (size_t)ch * 16;
                uint32_t dst = smem_base + OFF_B + (uint32_t)ns * B_STRIDE
                             + SWZ128((uint32_t)(f * 128 + ch * 16));
                CP16(dst, src);
            }
            CP_COMMIT();
            CP_WAIT(1);    // chunk c's B complete; c+1 in flight
        } else {
            CP_WAIT(0);
        }
        __syncthreads();   // B[c] visible, A[c+1] built, stage s safe to read

        const uint32_t abase = smem_base + OFF_A + (uint32_t)s * A_STRIDE;
        const uint32_t bbase = smem_base + OFF_B + (uint32_t)s * B_STRIDE;

        #pragma unroll
        for (int kk = 0; kk < 4; kk++) {           // 4 x k16 = 64 k per stage
            const uint32_t kx = (uint32_t)(kk * 32);  // 16 fp16 = 32 bytes
            uint32_t afr[2][4];
            #pragma unroll
            for (int mt = 0; mt < 2; mt++)
                ldsm4(afr[mt], abase + (a_pre[mt] ^ kx));
            uint32_t bfr[4][4];
            #pragma unroll
            for (int g = 0; g < 4; g++)
                ldsm4(bfr[g], bbase + (b_pre[g] ^ kx));
            #pragma unroll
            for (int mt = 0; mt < 2; mt++)
                #pragma unroll
                for (int nt = 0; nt < 8; nt++)
                    mma16(acc[mt][nt], afr[mt], bfr[nt >> 1][(nt & 1) * 2],
                          bfr[nt >> 1][(nt & 1) * 2 + 1]);
        }
        __syncthreads();   // all warps done with stage s before next build
    }

    // ---- fused epilogue: bias + ReLU + dense[512x4] ----
    {
        const float* bs = (const float*)(smem + OFF_BIAS);
        const float4* ws = (const float4*)(smem + OFF_W);
        const int g = lane >> 2;
        const int cp = lane & 3;

        // per-thread partials for 4 row contexts (mt,h): rows wm*32 + mt*16 + h*8 + g
        float4 part[2][2];
        #pragma unroll
        for (int mt = 0; mt < 2; mt++)
            #pragma unroll
            for (int h = 0; h < 2; h++) {
                float4 p = make_float4(0.f, 0.f, 0.f, 0.f);
                #pragma unroll
                for (int nt = 0; nt < 8; nt++) {
                    int f0 = wn * 64 + nt * 8 + 2 * cp;
                    float v0 = fmaxf(acc[mt][nt][h * 2 + 0] + bs[f0], 0.0f);
                    float v1 = fmaxf(acc[mt][nt][h * 2 + 1] + bs[f0 + 1], 0.0f);
                    float4 w0 = ws[f0];
                    float4 w1 = ws[f0 + 1];
                    p.x += v0 * w0.x + v1 * w1.x;
                    p.y += v0 * w0.y + v1 * w1.y;
                    p.z += v0 * w0.z + v1 * w1.z;
                    p.w += v0 * w0.w + v1 * w1.w;
                }
                part[mt][h] = p;
            }
        // reduce over the 4 lanes sharing a row (cp = lane&3)
        #pragma unroll
        for (int mt = 0; mt < 2; mt++)
            #pragma unroll
            for (int h = 0; h < 2; h++) {
                #pragma unroll
                for (int d = 1; d < 4; d <<= 1) {
                    part[mt][h].x += __shfl_xor_sync(0xFFFFFFFF, part[mt][h].x, d);
                    part[mt][h].y += __shfl_xor_sync(0xFFFFFFFF, part[mt][h].y, d);
                    part[mt][h].z += __shfl_xor_sync(0xFFFFFFFF, part[mt][h].z, d);
                    part[mt][h].w += __shfl_xor_sync(0xFFFFFFFF, part[mt][h].w, d);
                }
            }
        __syncthreads();   // done reading A stages; reuse OFF_A as P buffer
        float4* P = (float4*)(smem + OFF_A);   // [64 rows][8 wn]
        if (cp == 0) {
            #pragma unroll
            for (int mt = 0; mt < 2; mt++)
                #pragma unroll
                for (int h = 0; h < 2; h++) {
                    int row = wm * 32 + mt * 16 + h * 8 + g;
                    P[row * 8 + wn] = part[mt][h];
                }
        }
        __syncthreads();

        if (tid < M_TILE) {
            float4 db = *(const float4*)dense_b;
            float4 o = db;
            #pragma unroll
            for (int w = 0; w < 8; w++) {
                float4 p = P[tid * 8 + w];
                o.x += p.x; o.y += p.y; o.z += p.z; o.w += p.w;
            }
            ((float4*)out)[(size_t)b * L_SZ + T0 + tid] = o;
        }
    }
}

extern "C" void kernel_launch(void* const* d_in, const int* in_sizes, int n_in,
                              void* d_out, int out_size) {
    const int*   example = (const int*)d_in[0];
    const float* kern    = (const float*)d_in[1];
    const float* bias    = (const float*)d_in[2];
    const float* dense_w = (const float*)d_in[3];
    const float* dense_b = (const float*)d_in[4];
    float* out = (float*)d_out;

    cudaFuncSetAttribute(conv_fused_kernel,
                         cudaFuncAttributeMaxDynamicSharedMemorySize, SMEM_TOTAL);

    // 1) round conv weights to fp16-RN into static scratch
    {
        size_t n = (size_t)F_SZ * L_SZ;
        int blocks = (int)((n + 255) / 256);
        round_fp16_kernel<<<blocks, 256>>>(kern);
    }
    // 2) fused Toeplitz-GEMM + bias + ReLU + dense
    conv_fused_kernel<<<B_SZ * N_TILES_CTA, NTHREADS, SMEM_TOTAL>>>(
        example, bias, dense_w, dense_b, out);
}

// round 12
// speedup vs baseline: 1.8894x; 1.0076x over previous
#include <cuda_runtime.h>
#include <cuda_fp16.h>
#include <cstdint>
#include <cstddef>

#define B_SZ 8
#define L_SZ 12288
#define F_SZ 512
#define NTHREADS 512
#define M_TILE 64
#define N_TILES_CTA 192   /* L / M_TILE */
#define KC 32             /* k elements per chunk (64B rows in fp16, SW64) */

// fp16-rounded copy of the conv kernel weights (12.5MB static device scratch)
__device__ __half g_Khf[(size_t)F_SZ * L_SZ];

// ---------------- helpers ----------------
__device__ __forceinline__ uint32_t smem_u32(const void* p) {
    uint32_t a;
    asm("{ .reg .u64 t; cvta.to.shared.u64 t, %1; cvt.u32.u64 %0, t; }" : "=r"(a) : "l"(p));
    return a;
}
#define SWZ64(o) ((o) ^ (((o) >> 3) & 0x30))

#define CP16(dst, src) \
    asm volatile("cp.async.cg.shared.global [%0], [%1], 16;" :: "r"(dst), "l"(src))
#define CP_COMMIT() asm volatile("cp.async.commit_group;" ::: "memory")
#define CP_WAIT(N) asm volatile("cp.async.wait_group %0;" :: "n"(N) : "memory")

__device__ __forceinline__ void ldsm4(uint32_t* r, uint32_t addr) {
    asm volatile("ldmatrix.sync.aligned.m8n8.x4.shared.b16 {%0,%1,%2,%3}, [%4];"
                 : "=r"(r[0]), "=r"(r[1]), "=r"(r[2]), "=r"(r[3]) : "r"(addr));
}

__device__ __forceinline__ void mma16(float* c, const uint32_t* a, uint32_t b0, uint32_t b1) {
    asm volatile(
        "mma.sync.aligned.m16n8k16.row.col.f32.f16.f16.f32 "
        "{%0,%1,%2,%3}, {%4,%5,%6,%7}, {%8,%9}, {%0,%1,%2,%3};"
        : "+f"(c[0]), "+f"(c[1]), "+f"(c[2]), "+f"(c[3])
        : "r"(a[0]), "r"(a[1]), "r"(a[2]), "r"(a[3]), "r"(b0), "r"(b1));
}

// ---------------- preprocess: round K to fp16 (round-to-nearest) ----------------
__global__ void round_fp16_kernel(const float* __restrict__ K) {
    size_t i = (size_t)blockIdx.x * blockDim.x + threadIdx.x;
    if (i < (size_t)F_SZ * L_SZ) {
        g_Khf[i] = __float2half_rn(K[i]);
    }
}

// ---------------- SMEM layout (bytes from dynamic smem base) ----------------
#define OFF_BIAS    0u        /* 512*4  = 2048  */
#define OFF_W       2048u     /* 512*16 = 8192  -> 10240 */
#define OFF_X       10240u    /* 12288*4= 49152 -> 59392 */
#define OFF_A       59392u    /* 4 * 4096  = 16384 -> 75776  (1024-aligned) */
#define OFF_B       75776u    /* 4 * 32768 = 131072 -> 206848 (1024-aligned) */
#define A_STRIDE    4096u
#define B_STRIDE    32768u
#define SMEM_TOTAL  206848u

// ---------------- main fused kernel ----------------
__global__ void __launch_bounds__(NTHREADS, 1)
conv_fused_kernel(const int* __restrict__ example,
                  const float* __restrict__ bias,
                  const float* __restrict__ dense_w,
                  const float* __restrict__ dense_b,
                  float* __restrict__ out) {
    extern __shared__ char smem[];
    const uint32_t smem_base = smem_u32(smem);
    const int tid = threadIdx.x;
    const int wid = tid >> 5;
    const int lane = tid & 31;
    const int wm = wid >> 3;       // 0..1  (M position: 32 rows per warp)
    const int wn = wid & 7;        // 0..7  (N position: 64 filters per warp)

    // LPT schedule: heavy tiles (large T0) first
    const int i_tile = (N_TILES_CTA - 1) - (int)(blockIdx.x >> 3);
    const int b = (int)(blockIdx.x & 7);
    const int T0 = i_tile * M_TILE;
    const int C = (T0 >> 5) + 2;   // 32-wide j-chunks (j <= T0+63)

    // ---- stage bias, dense_w, x into SMEM ----
    {
        float* bs = (float*)(smem + OFF_BIAS);
        for (int f = tid; f < F_SZ; f += NTHREADS) bs[f] = bias[f];
        float4* ws = (float4*)(smem + OFF_W);
        const float4* wg = (const float4*)dense_w;
        for (int f = tid; f < F_SZ; f += NTHREADS) ws[f] = wg[f];
        const int4* e4 = (const int4*)(example + (size_t)b * L_SZ);
        float4* xs4 = (float4*)(smem + OFF_X);
        for (int k = tid; k < L_SZ / 4; k += NTHREADS) {
            int4 v = e4[k];
            float4 f;
            f.x = (float)v.x * 0.5f - 1.0f;
            f.y = (float)v.y * 0.5f - 1.0f;
            f.z = (float)v.z * 0.5f - 1.0f;
            f.w = (float)v.w * 0.5f - 1.0f;
            xs4[k] = f;
        }
    }
    __syncthreads();

    const float* xs = (const float*)(smem + OFF_X);

    // ---- precomputed ldmatrix lane offsets (SW64, XOR-composed) ----
    // addr = rowbase + ((static_col ^ swz) ^ kx); all column bits stay < 64 (no carry).
    // A frag rows mt=0: row = wm*32 + (lane&15); static col = ((lane>>4)<<4)
    uint32_t a_pre, a_boot;
    {
        uint32_t rowbase = (uint32_t)(wm * 32 + (lane & 15)) * 64u;
        uint32_t swz = (rowbase >> 3) & 0x30u;
        uint32_t col = (uint32_t)((lane >> 4) << 4);
        a_pre = rowbase + (col ^ swz);
        // bootstrap frag(mt=1, kk=0): rows +16
        uint32_t rb2 = rowbase + 16u * 64u;
        uint32_t swz2 = (rb2 >> 3) & 0x30u;
        a_boot = rb2 + (col ^ swz2);
    }
    // B frag (n16 group g): n = wn*64 + g*16 + (lane&7) + (((lane>>4)&1)<<3);
    // static col byte = ((lane>>3)&1)<<4
    uint32_t b_pre[4];
    #pragma unroll
    for (int g = 0; g < 4; g++) {
        uint32_t n = (uint32_t)(wn * 64 + g * 16 + (lane & 7) + (((lane >> 4) & 1) << 3));
        uint32_t rowbase = n * 64u;
        uint32_t swz = (rowbase >> 3) & 0x30u;
        uint32_t col = (uint32_t)(((lane >> 3) & 1) << 4);
        b_pre[g] = rowbase + (col ^ swz);
    }

    // A build mapping: thread t covers row = t>>3, k-cols (t&7)*4 .. +3 (8 bytes fp16)
    const int arow = tid >> 3;
    const int acol = (tid & 7) * 4;

    float acc[2][8][4];
    #pragma unroll
    for (int mt = 0; mt < 2; mt++)
        #pragma unroll
        for (int nt = 0; nt < 8; nt++)
            #pragma unroll
            for (int k = 0; k < 4; k++) acc[mt][nt][k] = 0.0f;

    // ---- chunk builder: issue B cp.async first, then A stores, then commit ----
    auto build_chunk = [&](int j, int st) {
        const int J = j * KC;
        // B: K[0:512, J:J+32] fp16, 64B rows, SW64
        #pragma unroll
        for (int q = 0; q < 4; q++) {
            int linear = tid + q * NTHREADS;   // 0..2047
            int f = linear >> 2;
            int ch = linear & 3;
            const char* src = (const char*)g_Khf + (size_t)f * (L_SZ * 2)
                            + (size_t)J * 2 + (size_t)ch * 16;
            uint32_t o = (uint32_t)(f * 64 + ch * 16);
            uint32_t dst = smem_base + OFF_B + (uint32_t)st * B_STRIDE + SWZ64(o);
            CP16(dst, src);
        }
        // A: A[r,k] = x[T0 + r - J - k], zero if negative
        {
            char* Ab = smem + OFF_A + st * A_STRIDE;
            int i0 = T0 + arow - J - acol;
            __half2 h01 = __halves2half2(
                __float2half_rn((i0     >= 0) ? xs[i0]     : 0.0f),
                __float2half_rn((i0 - 1 >= 0) ? xs[i0 - 1] : 0.0f));
            __half2 h23 = __halves2half2(
                __float2half_rn((i0 - 2 >= 0) ? xs[i0 - 2] : 0.0f),
                __float2half_rn((i0 - 3 >= 0) ? xs[i0 - 3] : 0.0f));
            uint2 v;
            v.x = *(const uint32_t*)&h01;
            v.y = *(const uint32_t*)&h23;
            uint32_t o = (uint32_t)(arow * 64 + acol * 2);
            *(uint2*)(Ab + SWZ64(o)) = v;
        }
        CP_COMMIT();
    };

    // ---- prologue: build chunks 0 and 1 ----
    build_chunk(0, 0);
    if (C > 1) build_chunk(1, 1);

    uint32_t prev[4];   // rolling Toeplitz A fragment: frag(0, kk-1) == frag(1, kk)

    // ---- mainloop: one __syncthreads per chunk, 4-stage ring, prefetch depth 2 ----
    for (int c = 0; c < C; c++) {
        const int st = c & 3;

        if (c + 2 < C) {
            build_chunk(c + 2, (c + 2) & 3);
            CP_WAIT(2);          // groups c+1, c+2 may be pending; group c done
        } else if (c + 1 < C) {
            CP_WAIT(1);
        } else {
            CP_WAIT(0);
        }
        __syncthreads();         // B[c]+A[c] visible; stage (c+2)%4 was free (read at c-2)

        const uint32_t abase = smem_base + OFF_A + (uint32_t)st * A_STRIDE;
        const uint32_t bbase = smem_base + OFF_B + (uint32_t)st * B_STRIDE;

        if (c == 0) ldsm4(prev, abase + a_boot);   // bootstrap frag(1,0)

        #pragma unroll
        for (int kk = 0; kk < 2; kk++) {           // 2 x k16 = 32 k per chunk
            const uint32_t kx = (uint32_t)(kk * 32);
            uint32_t cur[4];
            ldsm4(cur, abase + (a_pre ^ kx));      // frag(0,kk) -> also frag(1,kk+1)
            uint32_t bfr[4][4];
            #pragma unroll
            for (int g = 0; g < 4; g++)
                ldsm4(bfr[g], bbase + (b_pre[g] ^ kx));
            #pragma unroll
            for (int nt = 0; nt < 8; nt++) {
                mma16(acc[0][nt], cur,  bfr[nt >> 1][(nt & 1) * 2],
                      bfr[nt >> 1][(nt & 1) * 2 + 1]);
                mma16(acc[1][nt], prev, bfr[nt >> 1][(nt & 1) * 2],
                      bfr[nt >> 1][(nt & 1) * 2 + 1]);
            }
            #pragma unroll
            for (int r = 0; r < 4; r++) prev[r] = cur[r];
        }
    }
    __syncthreads();   // all reads of SMEM stages done before epilogue reuses OFF_A

    // ---- fused epilogue: bias + ReLU + dense[512x4] ----
    {
        const float* bs = (const float*)(smem + OFF_BIAS);
        const float4* ws = (const float4*)(smem + OFF_W);
        const int g = lane >> 2;
        const int cp = lane & 3;

        // per-thread partials for 4 row contexts (mt,h): rows wm*32 + mt*16 + h*8 + g
        float4 part[2][2];
        #pragma unroll
        for (int mt = 0; mt < 2; mt++)
            #pragma unroll
            for (int h = 0; h < 2; h++) {
                float4 p = make_float4(0.f, 0.f, 0.f, 0.f);
                #pragma unroll
                for (int nt = 0; nt < 8; nt++) {
                    int f0 = wn * 64 + nt * 8 + 2 * cp;
                    float v0 = fmaxf(acc[mt][nt][h * 2 + 0] + bs[f0], 0.0f);
                    float v1 = fmaxf(acc[mt][nt][h * 2 + 1] + bs[f0 + 1], 0.0f);
                    float4 w0 = ws[f0];
                    float4 w1 = ws[f0 + 1];
                    p.x += v0 * w0.x + v1 * w1.x;
                    p.y += v0 * w0.y + v1 * w1.y;
                    p.z += v0 * w0.z + v1 * w1.z;
                    p.w += v0 * w0.w + v1 * w1.w;
                }
                part[mt][h] = p;
            }
        // reduce over the 4 lanes sharing a row (cp = lane&3)
        #pragma unroll
        for (int mt = 0; mt < 2; mt++)
            #pragma unroll
            for (int h = 0; h < 2; h++) {
                #pragma unroll
                for (int d = 1; d < 4; d <<= 1) {
                    part[mt][h].x += __shfl_xor_sync(0xFFFFFFFF, part[mt][h].x, d);
                    part[mt][h].y += __shfl_xor_sync(0xFFFFFFFF, part[mt][h].y, d);
                    part[mt][h].z += __shfl_xor_sync(0xFFFFFFFF, part[mt][h].z, d);
                    part[mt][h].w += __shfl_xor_sync(0xFFFFFFFF, part[mt][h].w, d);
                }
            }
        float4* P = (float4*)(smem + OFF_A);   // [64 rows][8 wn] = 8KB scratch
        if (cp == 0) {
            #pragma unroll
            for (int mt = 0; mt < 2; mt++)
                #pragma unroll
                for (int h = 0; h < 2; h++) {
                    int row = wm * 32 + mt * 16 + h * 8 + g;
                    P[row * 8 + wn] = part[mt][h];
                }
        }
        __syncthreads();

        if (tid < M_TILE) {
            float4 db = *(const float4*)dense_b;
            float4 o = db;
            #pragma unroll
            for (int w = 0; w < 8; w++) {
                float4 p = P[tid * 8 + w];
                o.x += p.x; o.y += p.y; o.z += p.z; o.w += p.w;
            }
            ((float4*)out)[(size_t)b * L_SZ + T0 + tid] = o;
        }
    }
}

extern "C" void kernel_launch(void* const* d_in, const int* in_sizes, int n_in,
                              void* d_out, int out_size) {
    const int*   example = (const int*)d_in[0];
    const float* kern    = (const float*)d_in[1];
    const float* bias    = (const float*)d_in[2];
    const float* dense_w = (const float*)d_in[3];
    const float* dense_b = (const float*)d_in[4];
    float* out = (float*)d_out;

    cudaFuncSetAttribute(conv_fused_kernel,
                         cudaFuncAttributeMaxDynamicSharedMemorySize, SMEM_TOTAL);

    // 1) round conv weights to fp16-RN into static scratch
    {
        size_t n = (size_t)F_SZ * L_SZ;
        int blocks = (int)((n + 255) / 256);
        round_fp16_kernel<<<blocks, 256>>>(kern);
    }
    // 2) fused Toeplitz-GEMM + bias + ReLU + dense
    conv_fused_kernel<<<B_SZ * N_TILES_CTA, NTHREADS, SMEM_TOTAL>>>(
        example, bias, dense_w, dense_b, out);
}